// round 5
// baseline (speedup 1.0000x reference)
#include <cuda_runtime.h>
#include <stdint.h>

// HashEmbedderOptimized: instant-NGP multires hash encoding.
// x (1048576 x 3, f32); tables (16 x 524288 x 2) stored as FLOAT32 in device
// memory (bf16-valued, upcast by harness — established by R1-R4 error forensics).
// out (1048576 x 32) f32, out[p*32 + level*2 + feat].

#define N_POINTS 1048576u
#define TSIZE    524288u
#define HMASK    524287u
#define P1 2654435761u
#define P2 805459861u

__global__ void __launch_bounds__(256) hashgrid_kernel(
    const float*  __restrict__ x,
    const float2* __restrict__ tables,   // one float2 = (feat0, feat1) per entry
    float* __restrict__ out)
{
    const unsigned p = blockIdx.x * 256u + threadIdx.x;
    if (p >= N_POINTS) return;

    const float x0 = x[3u * p + 0];
    const float x1 = x[3u * p + 1];
    const float x2 = x[3u * p + 2];
    const float xc0 = __saturatef(x0);
    const float xc1 = __saturatef(x1);
    const float xc2 = __saturatef(x2);

    // floor(16 * (2^(1/3))^l) computed in float64 by the reference setup
    constexpr float RES[16] = {16.f, 20.f, 25.f, 32.f, 40.f, 50.f, 64.f, 80.f,
                               101.f, 128.f, 161.f, 203.f, 256.f, 322.f, 406.f, 512.f};

    float acc[32];

#pragma unroll
    for (int l = 0; l < 16; ++l) {
        const float res  = RES[l];
        const float grid = 1.0f / res;   // fl32(1/res), same as reference's (1-0)/res

        // bl = floor(xc / grid): exact rounding — voxel index is discrete.
        const float blf0 = floorf(__fdiv_rn(xc0, grid));
        const float blf1 = floorf(__fdiv_rn(xc1, grid));
        const float blf2 = floorf(__fdiv_rn(xc2, grid));

        const uint32_t b0 = (uint32_t)blf0;
        const uint32_t b1 = (uint32_t)blf1;
        const uint32_t b2 = (uint32_t)blf2;

        // w = (x - bl*grid)/grid ; continuous, so *res (1 ulp from /grid) is fine
        const float w0 = (x0 - blf0 * grid) * res;
        const float w1 = (x1 - blf1 * grid) * res;
        const float w2 = (x2 - blf2 * grid) * res;
        const float o0 = 1.0f - w0;
        const float o1 = 1.0f - w1;
        const float o2 = 1.0f - w2;

        // hash components (uint32 wraparound; +P distributes over the sum)
        const uint32_t h1  = b1 * P1;
        const uint32_t h1p = h1 + P1;
        const uint32_t h2  = b2 * P2;
        const uint32_t h2p = h2 + P2;
        const uint32_t b0p = b0 + 1u;

        const float2* __restrict__ tl = tables + (size_t)l * TSIZE;

        const float2 e000 = __ldg(&tl[(b0  ^ h1  ^ h2 ) & HMASK]);
        const float2 e001 = __ldg(&tl[(b0  ^ h1  ^ h2p) & HMASK]);
        const float2 e010 = __ldg(&tl[(b0  ^ h1p ^ h2 ) & HMASK]);
        const float2 e011 = __ldg(&tl[(b0  ^ h1p ^ h2p) & HMASK]);
        const float2 e100 = __ldg(&tl[(b0p ^ h1  ^ h2 ) & HMASK]);
        const float2 e101 = __ldg(&tl[(b0p ^ h1  ^ h2p) & HMASK]);
        const float2 e110 = __ldg(&tl[(b0p ^ h1p ^ h2 ) & HMASK]);
        const float2 e111 = __ldg(&tl[(b0p ^ h1p ^ h2p) & HMASK]);

        // trilinear coefficients: corner (i,j,k) -> (i?w0:1-w0)(j?w1:1-w1)(k?w2:1-w2)
        const float caa = o1 * o2;
        const float cab = o1 * w2;
        const float cba = w1 * o2;
        const float cbb = w1 * w2;

        const float c000 = o0 * caa, c001 = o0 * cab, c010 = o0 * cba, c011 = o0 * cbb;
        const float c100 = w0 * caa, c101 = w0 * cab, c110 = w0 * cba, c111 = w0 * cbb;

        float f0 = c000 * e000.x;
        f0 = fmaf(c001, e001.x, f0);
        f0 = fmaf(c010, e010.x, f0);
        f0 = fmaf(c011, e011.x, f0);
        f0 = fmaf(c100, e100.x, f0);
        f0 = fmaf(c101, e101.x, f0);
        f0 = fmaf(c110, e110.x, f0);
        f0 = fmaf(c111, e111.x, f0);

        float f1 = c000 * e000.y;
        f1 = fmaf(c001, e001.y, f1);
        f1 = fmaf(c010, e010.y, f1);
        f1 = fmaf(c011, e011.y, f1);
        f1 = fmaf(c100, e100.y, f1);
        f1 = fmaf(c101, e101.y, f1);
        f1 = fmaf(c110, e110.y, f1);
        f1 = fmaf(c111, e111.y, f1);

        acc[2 * l + 0] = f0;
        acc[2 * l + 1] = f1;
    }

    float4* o = reinterpret_cast<float4*>(out + (size_t)p * 32u);
#pragma unroll
    for (int j = 0; j < 8; ++j)
        o[j] = make_float4(acc[4 * j + 0], acc[4 * j + 1], acc[4 * j + 2], acc[4 * j + 3]);
}

extern "C" void kernel_launch(void* const* d_in, const int* in_sizes, int n_in,
                              void* d_out, int out_size)
{
    // x = 3145728 elems, tables = 16777216 elems; select by size for safety.
    int xi = 0, ti = 1;
    if (n_in >= 2 && in_sizes[0] > in_sizes[1]) { xi = 1; ti = 0; }

    const float*  xin = (const float*)d_in[xi];
    const float2* tab = (const float2*)d_in[ti];
    float*        out = (float*)d_out;

    const unsigned nblocks = (N_POINTS + 255u) / 256u;
    hashgrid_kernel<<<nblocks, 256>>>(xin, tab, out);
}

// round 6
// speedup vs baseline: 1.6136x; 1.6136x over previous
#include <cuda_runtime.h>
#include <stdint.h>

// HashEmbedderOptimized R6: spatial counting-sort (32^3 Morton buckets) +
// coherent gather. Core per-point math bit-identical to R5 (passing).
// x (1048576 x 3, f32); tables (16 x 524288 x 2) stored as f32 pairs.
// out (1048576 x 32) f32.

#define NPTS   1048576u
#define TSIZE  524288u
#define HMASK  524287u
#define P1     2654435761u
#define P2     805459861u
#define NBUCK  32768u           // 32^3 Morton buckets

__device__ uint32_t g_hist[NBUCK];
__device__ uint32_t g_off[NBUCK];
__device__ uint32_t g_perm[NPTS];
__device__ float    g_xs0[NPTS];
__device__ float    g_xs1[NPTS];
__device__ float    g_xs2[NPTS];

__device__ __forceinline__ uint32_t part1by2(uint32_t v) {
    // spread low 5 bits to every 3rd bit
    v &= 0x3FFu;
    v = (v | (v << 16)) & 0x030000FFu;
    v = (v | (v << 8))  & 0x0300F00Fu;
    v = (v | (v << 4))  & 0x030C30C3u;
    v = (v | (v << 2))  & 0x09249249u;
    return v;
}

__device__ __forceinline__ uint32_t bucket_key(float x0, float x1, float x2) {
    const float c0 = __saturatef(x0), c1 = __saturatef(x1), c2 = __saturatef(x2);
    uint32_t i0 = (uint32_t)(c0 * 32.0f); if (i0 > 31u) i0 = 31u;
    uint32_t i1 = (uint32_t)(c1 * 32.0f); if (i1 > 31u) i1 = 31u;
    uint32_t i2 = (uint32_t)(c2 * 32.0f); if (i2 > 31u) i2 = 31u;
    return part1by2(i0) | (part1by2(i1) << 1) | (part1by2(i2) << 2);
}

// ---- K1: zero histogram ----
__global__ void k_zero() {
    const unsigned i = blockIdx.x * blockDim.x + threadIdx.x;
    if (i < NBUCK) g_hist[i] = 0u;
}

// ---- K2: histogram ----
__global__ void __launch_bounds__(256) k_hist(const float* __restrict__ x) {
    const unsigned p = blockIdx.x * 256u + threadIdx.x;
    if (p >= NPTS) return;
    const uint32_t key = bucket_key(x[3u*p+0], x[3u*p+1], x[3u*p+2]);
    atomicAdd(&g_hist[key], 1u);
}

// ---- K3: exclusive prefix sum (single block, 1024 threads x 32 elems) ----
__global__ void __launch_bounds__(1024) k_scan() {
    __shared__ uint32_t sm[1024];
    const unsigned t = threadIdx.x;
    const unsigned base = t * 32u;
    uint32_t loc[32];
    uint32_t s = 0;
#pragma unroll
    for (int i = 0; i < 32; ++i) { loc[i] = g_hist[base + i]; s += loc[i]; }
    sm[t] = s;
    __syncthreads();
#pragma unroll
    for (unsigned off = 1; off < 1024; off <<= 1) {
        uint32_t v = (t >= off) ? sm[t - off] : 0u;
        __syncthreads();
        sm[t] += v;
        __syncthreads();
    }
    uint32_t run = sm[t] - s;   // exclusive base of this chunk
#pragma unroll
    for (int i = 0; i < 32; ++i) { g_off[base + i] = run; run += loc[i]; }
}

// ---- K4: scatter into sorted order ----
__global__ void __launch_bounds__(256) k_scatter(const float* __restrict__ x) {
    const unsigned p = blockIdx.x * 256u + threadIdx.x;
    if (p >= NPTS) return;
    const float x0 = x[3u*p+0], x1 = x[3u*p+1], x2 = x[3u*p+2];
    const uint32_t key  = bucket_key(x0, x1, x2);
    const uint32_t slot = atomicAdd(&g_off[key], 1u);
    g_perm[slot] = p;
    g_xs0[slot] = x0;
    g_xs1[slot] = x1;
    g_xs2[slot] = x2;
}

// ---- K5: main gather over sorted points ----
__global__ void __launch_bounds__(256) k_gather(
    const float2* __restrict__ tables,
    float* __restrict__ out)
{
    const unsigned s = blockIdx.x * 256u + threadIdx.x;
    const unsigned lane = threadIdx.x & 31u;
    const unsigned warp = threadIdx.x >> 5;

    const float x0 = g_xs0[s];
    const float x1 = g_xs1[s];
    const float x2 = g_xs2[s];
    const uint32_t p = g_perm[s];

    const float xc0 = __saturatef(x0);
    const float xc1 = __saturatef(x1);
    const float xc2 = __saturatef(x2);

    constexpr float RES[16] = {16.f, 20.f, 25.f, 32.f, 40.f, 50.f, 64.f, 80.f,
                               101.f, 128.f, 161.f, 203.f, 256.f, 322.f, 406.f, 512.f};

    float acc[32];

#pragma unroll
    for (int l = 0; l < 16; ++l) {
        const float res  = RES[l];
        const float grid = 1.0f / res;

        const float blf0 = floorf(__fdiv_rn(xc0, grid));
        const float blf1 = floorf(__fdiv_rn(xc1, grid));
        const float blf2 = floorf(__fdiv_rn(xc2, grid));

        const uint32_t b0 = (uint32_t)blf0;
        const uint32_t b1 = (uint32_t)blf1;
        const uint32_t b2 = (uint32_t)blf2;

        const float w0 = (x0 - blf0 * grid) * res;
        const float w1 = (x1 - blf1 * grid) * res;
        const float w2 = (x2 - blf2 * grid) * res;
        const float o0 = 1.0f - w0;
        const float o1 = 1.0f - w1;
        const float o2 = 1.0f - w2;

        const uint32_t h1  = b1 * P1;
        const uint32_t h1p = h1 + P1;
        const uint32_t h2  = b2 * P2;
        const uint32_t h2p = h2 + P2;
        const uint32_t b0p = b0 + 1u;

        const float2* __restrict__ tl = tables + (size_t)l * TSIZE;

        const float2 e000 = __ldg(&tl[(b0  ^ h1  ^ h2 ) & HMASK]);
        const float2 e001 = __ldg(&tl[(b0  ^ h1  ^ h2p) & HMASK]);
        const float2 e010 = __ldg(&tl[(b0  ^ h1p ^ h2 ) & HMASK]);
        const float2 e011 = __ldg(&tl[(b0  ^ h1p ^ h2p) & HMASK]);
        const float2 e100 = __ldg(&tl[(b0p ^ h1  ^ h2 ) & HMASK]);
        const float2 e101 = __ldg(&tl[(b0p ^ h1  ^ h2p) & HMASK]);
        const float2 e110 = __ldg(&tl[(b0p ^ h1p ^ h2 ) & HMASK]);
        const float2 e111 = __ldg(&tl[(b0p ^ h1p ^ h2p) & HMASK]);

        const float caa = o1 * o2;
        const float cab = o1 * w2;
        const float cba = w1 * o2;
        const float cbb = w1 * w2;

        const float c000 = o0 * caa, c001 = o0 * cab, c010 = o0 * cba, c011 = o0 * cbb;
        const float c100 = w0 * caa, c101 = w0 * cab, c110 = w0 * cba, c111 = w0 * cbb;

        float f0 = c000 * e000.x;
        f0 = fmaf(c001, e001.x, f0);
        f0 = fmaf(c010, e010.x, f0);
        f0 = fmaf(c011, e011.x, f0);
        f0 = fmaf(c100, e100.x, f0);
        f0 = fmaf(c101, e101.x, f0);
        f0 = fmaf(c110, e110.x, f0);
        f0 = fmaf(c111, e111.x, f0);

        float f1 = c000 * e000.y;
        f1 = fmaf(c001, e001.y, f1);
        f1 = fmaf(c010, e010.y, f1);
        f1 = fmaf(c011, e011.y, f1);
        f1 = fmaf(c100, e100.y, f1);
        f1 = fmaf(c101, e101.y, f1);
        f1 = fmaf(c110, e110.y, f1);
        f1 = fmaf(c111, e111.y, f1);

        acc[2 * l + 0] = f0;
        acc[2 * l + 1] = f1;
    }

    // ---- wavefront-optimal scattered row write ----
    // Stage transposed in smem: st[warp][f*33 + lane]; then 8 lanes cooperate
    // per 128B output row (4 rows per iteration, conflict-free LDS by
    // construction: bank = (4*(lane%8) + lane/8 + ...) is a bijection mod 32).
    __shared__ float st[8][33 * 32];
    float* w_st = st[warp];
#pragma unroll
    for (int f = 0; f < 32; ++f) w_st[f * 33 + lane] = acc[f];
    __syncwarp();

    const unsigned sub  = lane & 7u;        // 8 lanes per row
    const unsigned rsub = lane >> 3;        // 4 rows per iteration
#pragma unroll
    for (int it = 0; it < 8; ++it) {
        const unsigned row = it * 4u + rsub;                 // point (lane) within warp
        const uint32_t prow = __shfl_sync(0xFFFFFFFFu, p, row);
        const unsigned c = sub * 4u;                          // feature start
        float4 v;
        v.x = w_st[(c + 0u) * 33u + row];
        v.y = w_st[(c + 1u) * 33u + row];
        v.z = w_st[(c + 2u) * 33u + row];
        v.w = w_st[(c + 3u) * 33u + row];
        *reinterpret_cast<float4*>(out + (size_t)prow * 32u + c) = v;
    }
}

extern "C" void kernel_launch(void* const* d_in, const int* in_sizes, int n_in,
                              void* d_out, int out_size)
{
    int xi = 0, ti = 1;
    if (n_in >= 2 && in_sizes[0] > in_sizes[1]) { xi = 1; ti = 0; }

    const float*  xin = (const float*)d_in[xi];
    const float2* tab = (const float2*)d_in[ti];
    float*        out = (float*)d_out;

    k_zero<<<(NBUCK + 1023u) / 1024u, 1024>>>();
    k_hist<<<NPTS / 256u, 256>>>(xin);
    k_scan<<<1, 1024>>>();
    k_scatter<<<NPTS / 256u, 256>>>(xin);
    k_gather<<<NPTS / 256u, 256>>>(tab, out);
}

// round 7
// speedup vs baseline: 1.6396x; 1.0161x over previous
#include <cuda_runtime.h>
#include <stdint.h>

// HashEmbedderOptimized R7: Morton sort (32^3) + coherent gather.
// Changes vs R6: (a) voxel index via floorf(xc*res) instead of __fdiv_rn
// (continuity of trilinear interp makes boundary mismatches O(1e-11)),
// (b) scatter packs (x,y,z,perm) into one float4 -> 1 wavefront/pt.

#define NPTS   1048576u
#define TSIZE  524288u
#define HMASK  524287u
#define P1     2654435761u
#define P2     805459861u
#define NBUCK  32768u           // 32^3 Morton buckets

__device__ uint32_t g_hist[NBUCK];
__device__ uint32_t g_off[NBUCK];
__device__ float4   g_xs[NPTS];     // (x0, x1, x2, perm-as-bits)

__device__ __forceinline__ uint32_t part1by2(uint32_t v) {
    v &= 0x3FFu;
    v = (v | (v << 16)) & 0x030000FFu;
    v = (v | (v << 8))  & 0x0300F00Fu;
    v = (v | (v << 4))  & 0x030C30C3u;
    v = (v | (v << 2))  & 0x09249249u;
    return v;
}

__device__ __forceinline__ uint32_t bucket_key(float x0, float x1, float x2) {
    const float c0 = __saturatef(x0), c1 = __saturatef(x1), c2 = __saturatef(x2);
    uint32_t i0 = (uint32_t)(c0 * 32.0f); if (i0 > 31u) i0 = 31u;
    uint32_t i1 = (uint32_t)(c1 * 32.0f); if (i1 > 31u) i1 = 31u;
    uint32_t i2 = (uint32_t)(c2 * 32.0f); if (i2 > 31u) i2 = 31u;
    return part1by2(i0) | (part1by2(i1) << 1) | (part1by2(i2) << 2);
}

__global__ void k_zero() {
    const unsigned i = blockIdx.x * blockDim.x + threadIdx.x;
    if (i < NBUCK) g_hist[i] = 0u;
}

__global__ void __launch_bounds__(256) k_hist(const float* __restrict__ x) {
    const unsigned p = blockIdx.x * 256u + threadIdx.x;
    if (p >= NPTS) return;
    const uint32_t key = bucket_key(x[3u*p+0], x[3u*p+1], x[3u*p+2]);
    atomicAdd(&g_hist[key], 1u);
}

__global__ void __launch_bounds__(1024) k_scan() {
    __shared__ uint32_t sm[1024];
    const unsigned t = threadIdx.x;
    const unsigned base = t * 32u;
    uint32_t loc[32];
    uint32_t s = 0;
#pragma unroll
    for (int i = 0; i < 32; ++i) { loc[i] = g_hist[base + i]; s += loc[i]; }
    sm[t] = s;
    __syncthreads();
#pragma unroll
    for (unsigned off = 1; off < 1024; off <<= 1) {
        uint32_t v = (t >= off) ? sm[t - off] : 0u;
        __syncthreads();
        sm[t] += v;
        __syncthreads();
    }
    uint32_t run = sm[t] - s;
#pragma unroll
    for (int i = 0; i < 32; ++i) { g_off[base + i] = run; run += loc[i]; }
}

__global__ void __launch_bounds__(256) k_scatter(const float* __restrict__ x) {
    const unsigned p = blockIdx.x * 256u + threadIdx.x;
    if (p >= NPTS) return;
    const float x0 = x[3u*p+0], x1 = x[3u*p+1], x2 = x[3u*p+2];
    const uint32_t key  = bucket_key(x0, x1, x2);
    const uint32_t slot = atomicAdd(&g_off[key], 1u);
    g_xs[slot] = make_float4(x0, x1, x2, __uint_as_float(p));
}

__global__ void __launch_bounds__(256) k_gather(
    const float2* __restrict__ tables,
    float* __restrict__ out)
{
    const unsigned s = blockIdx.x * 256u + threadIdx.x;
    const unsigned lane = threadIdx.x & 31u;
    const unsigned warp = threadIdx.x >> 5;

    const float4 xp = g_xs[s];
    const float x0 = xp.x, x1 = xp.y, x2 = xp.z;
    const uint32_t p = __float_as_uint(xp.w);

    const float xc0 = __saturatef(x0);
    const float xc1 = __saturatef(x1);
    const float xc2 = __saturatef(x2);

    constexpr float RES[16] = {16.f, 20.f, 25.f, 32.f, 40.f, 50.f, 64.f, 80.f,
                               101.f, 128.f, 161.f, 203.f, 256.f, 322.f, 406.f, 512.f};

    float acc[32];

#pragma unroll
    for (int l = 0; l < 16; ++l) {
        const float res  = RES[l];
        const float grid = 1.0f / res;

        // floor(xc*res) ~ floor(RN(xc/grid)) to ~2ulp; any boundary mismatch
        // is masked by interpolation continuity (error ~1e-11 absolute).
        const float blf0 = floorf(xc0 * res);
        const float blf1 = floorf(xc1 * res);
        const float blf2 = floorf(xc2 * res);

        const uint32_t b0 = (uint32_t)blf0;
        const uint32_t b1 = (uint32_t)blf1;
        const uint32_t b2 = (uint32_t)blf2;

        const float w0 = (x0 - blf0 * grid) * res;
        const float w1 = (x1 - blf1 * grid) * res;
        const float w2 = (x2 - blf2 * grid) * res;
        const float o0 = 1.0f - w0;
        const float o1 = 1.0f - w1;
        const float o2 = 1.0f - w2;

        const uint32_t h1  = b1 * P1;
        const uint32_t h1p = h1 + P1;
        const uint32_t h2  = b2 * P2;
        const uint32_t h2p = h2 + P2;
        const uint32_t b0p = b0 + 1u;

        const float2* __restrict__ tl = tables + (size_t)l * TSIZE;

        const float2 e000 = __ldg(&tl[(b0  ^ h1  ^ h2 ) & HMASK]);
        const float2 e001 = __ldg(&tl[(b0  ^ h1  ^ h2p) & HMASK]);
        const float2 e010 = __ldg(&tl[(b0  ^ h1p ^ h2 ) & HMASK]);
        const float2 e011 = __ldg(&tl[(b0  ^ h1p ^ h2p) & HMASK]);
        const float2 e100 = __ldg(&tl[(b0p ^ h1  ^ h2 ) & HMASK]);
        const float2 e101 = __ldg(&tl[(b0p ^ h1  ^ h2p) & HMASK]);
        const float2 e110 = __ldg(&tl[(b0p ^ h1p ^ h2 ) & HMASK]);
        const float2 e111 = __ldg(&tl[(b0p ^ h1p ^ h2p) & HMASK]);

        const float caa = o1 * o2;
        const float cab = o1 * w2;
        const float cba = w1 * o2;
        const float cbb = w1 * w2;

        const float c000 = o0 * caa, c001 = o0 * cab, c010 = o0 * cba, c011 = o0 * cbb;
        const float c100 = w0 * caa, c101 = w0 * cab, c110 = w0 * cba, c111 = w0 * cbb;

        float f0 = c000 * e000.x;
        f0 = fmaf(c001, e001.x, f0);
        f0 = fmaf(c010, e010.x, f0);
        f0 = fmaf(c011, e011.x, f0);
        f0 = fmaf(c100, e100.x, f0);
        f0 = fmaf(c101, e101.x, f0);
        f0 = fmaf(c110, e110.x, f0);
        f0 = fmaf(c111, e111.x, f0);

        float f1 = c000 * e000.y;
        f1 = fmaf(c001, e001.y, f1);
        f1 = fmaf(c010, e010.y, f1);
        f1 = fmaf(c011, e011.y, f1);
        f1 = fmaf(c100, e100.y, f1);
        f1 = fmaf(c101, e101.y, f1);
        f1 = fmaf(c110, e110.y, f1);
        f1 = fmaf(c111, e111.y, f1);

        acc[2 * l + 0] = f0;
        acc[2 * l + 1] = f1;
    }

    // smem transpose -> 8 lanes per 128B output row, conflict-free
    __shared__ float st[8][33 * 32];
    float* w_st = st[warp];
#pragma unroll
    for (int f = 0; f < 32; ++f) w_st[f * 33 + lane] = acc[f];
    __syncwarp();

    const unsigned sub  = lane & 7u;
    const unsigned rsub = lane >> 3;
#pragma unroll
    for (int it = 0; it < 8; ++it) {
        const unsigned row = it * 4u + rsub;
        const uint32_t prow = __shfl_sync(0xFFFFFFFFu, p, row);
        const unsigned c = sub * 4u;
        float4 v;
        v.x = w_st[(c + 0u) * 33u + row];
        v.y = w_st[(c + 1u) * 33u + row];
        v.z = w_st[(c + 2u) * 33u + row];
        v.w = w_st[(c + 3u) * 33u + row];
        *reinterpret_cast<float4*>(out + (size_t)prow * 32u + c) = v;
    }
}

extern "C" void kernel_launch(void* const* d_in, const int* in_sizes, int n_in,
                              void* d_out, int out_size)
{
    int xi = 0, ti = 1;
    if (n_in >= 2 && in_sizes[0] > in_sizes[1]) { xi = 1; ti = 0; }

    const float*  xin = (const float*)d_in[xi];
    const float2* tab = (const float2*)d_in[ti];
    float*        out = (float*)d_out;

    k_zero<<<(NBUCK + 1023u) / 1024u, 1024>>>();
    k_hist<<<NPTS / 256u, 256>>>(xin);
    k_scan<<<1, 1024>>>();
    k_scatter<<<NPTS / 256u, 256>>>(xin);
    k_gather<<<NPTS / 256u, 256>>>(tab, out);
}